// round 3
// baseline (speedup 1.0000x reference)
#include <cuda_runtime.h>
#include <cuda_bf16.h>
#include <math.h>

// Problem constants (fixed by the reference)
#define B_DIM 128
#define S_DIM 512
#define K_DIM 137
#define D_DIM (2 * K_DIM)      // 274
#define NCONN (K_DIM - 1)      // 136
#define WARPS_PER_BLOCK 8
#define THREADS (WARPS_PER_BLOCK * 32)
#define N_PAIRS (B_DIM * (S_DIM / 2))          // 32768 (warp = one s-pair)
#define N_BLOCKS (N_PAIRS / WARPS_PER_BLOCK)   // 4096

#define FULL_MASK 0xffffffffu

// Allocation-free scratch: per-block partials + completion ticket counter.
__device__ float2   g_partials[N_BLOCKS];
__device__ unsigned g_counter;

// Bone term for one item: sum_k (e[k+1]-e[k])^2 over x and y, where lane
// holds e[k] for k = lane + 32*j (j<4) and k = 128+lane (j==4, lanes 0..8,
// zeros elsewhere). Warp-collective (call with warp-uniform control flow).
__device__ __forceinline__ float bone_reduce(const float ex[5], const float ey[5], int lane)
{
    float acc = 0.0f;
    #pragma unroll
    for (int j = 0; j < 4; j++) {
        float nx_dn = __shfl_down_sync(FULL_MASK, ex[j], 1);
        float ny_dn = __shfl_down_sync(FULL_MASK, ey[j], 1);
        float nx_w0 = __shfl_sync(FULL_MASK, ex[j + 1], 0);
        float ny_w0 = __shfl_sync(FULL_MASK, ey[j + 1], 0);
        float nx = (lane == 31) ? nx_w0 : nx_dn;
        float ny = (lane == 31) ? ny_w0 : ny_dn;
        float dx = nx - ex[j];
        float dy = ny - ey[j];
        acc = fmaf(dx, dx, acc);
        acc = fmaf(dy, dy, acc);
    }
    // k = 128..135 diffs live on lanes 0..7 (need e up to k=136 on lane 8)
    float nx_dn = __shfl_down_sync(FULL_MASK, ex[4], 1);
    float ny_dn = __shfl_down_sync(FULL_MASK, ey[4], 1);
    if (lane < 8) {
        float dx = nx_dn - ex[4];
        float dy = ny_dn - ey[4];
        acc = fmaf(dx, dx, acc);
        acc = fmaf(dy, dy, acc);
    }
    return acc;
}

// One warp handles the item pair (b, s0) and (b, s0+1).
// Target rows r0=s0, r1=s0+1, r2=s0+2 are loaded once:
//   bone(s0)  uses r0;  bone(s0+1) & pose(s0) use r1;  pose(s0+1) uses r2.
__global__ __launch_bounds__(THREADS) void t2p_fused_kernel(
    const float* __restrict__ pred,   // [128, 512, 274]
    const float* __restrict__ tgt,    // [128, 2, 512, 137]
    const int*   __restrict__ tlen,   // [128]
    float*       __restrict__ out)    // [3]
{
    __shared__ float    s_pose[WARPS_PER_BLOCK];
    __shared__ float    s_bone[WARPS_PER_BLOCK];
    __shared__ unsigned s_is_last;

    const int warp = threadIdx.x >> 5;
    const int lane = threadIdx.x & 31;
    const int pair = blockIdx.x * WARPS_PER_BLOCK + warp;
    const int b  = pair >> 8;             // 256 pairs per batch row
    const int s0 = (pair & 255) << 1;
    const int s1 = s0 + 1;

    float pose_sum = 0.0f;
    float bone_sum = 0.0f;

    const int L = __ldg(&tlen[b]);
    const bool v_b0 = (s0 < L);        // bone(s0); always true for s0==0 (L>=2)
    const bool v_b1 = (s1 < L);        // bone(s1) AND pose(s0)
    const bool v_p1 = (s1 < L - 1);    // pose(s1); implies v_b1

    if (v_b0) {
        const float2* __restrict__ p0 =
            (const float2*)(pred + (size_t)(b * S_DIM + s0) * D_DIM);
        const float2* __restrict__ p1 = p0 + K_DIM;  // row s1
        const float* __restrict__ t0 =
            tgt + ((size_t)(2 * b)     * S_DIM + s0) * K_DIM;  // x rows r0,r1,r2 contiguous
        const float* __restrict__ t1 =
            tgt + ((size_t)(2 * b + 1) * S_DIM + s0) * K_DIM;  // y rows

        // ---- Load phase: everything into registers, batched for MLP ----
        float p0x[5], p0y[5], p1x[5], p1y[5];
        float t00[5], t01[5], t02[5];   // t0 rows r0, r1, r2
        float t10[5], t11[5], t12[5];   // t1 rows r0, r1, r2

        #pragma unroll
        for (int j = 0; j < 5; j++) {
            const int  k  = (j < 4) ? (lane + 32 * j) : (128 + lane);
            const bool ok = (j < 4) || (lane < 9);

            p0x[j] = 0.0f; p0y[j] = 0.0f; p1x[j] = 0.0f; p1y[j] = 0.0f;
            t00[j] = 0.0f; t01[j] = 0.0f; t02[j] = 0.0f;
            t10[j] = 0.0f; t11[j] = 0.0f; t12[j] = 0.0f;

            if (ok) {
                float2 a = __ldg(p0 + k);
                p0x[j] = a.x; p0y[j] = a.y;
                t00[j] = __ldg(t0 + k);
                t10[j] = __ldg(t1 + k);
                if (v_b1) {
                    float2 c = __ldg(p1 + k);
                    p1x[j] = c.x; p1y[j] = c.y;
                    t01[j] = __ldg(t0 + k + K_DIM);
                    t11[j] = __ldg(t1 + k + K_DIM);
                }
                if (v_p1) {
                    t02[j] = __ldg(t0 + k + 2 * K_DIM);
                    t12[j] = __ldg(t1 + k + 2 * K_DIM);
                }
            }
        }

        // ---- Compute phase ----
        // bone(s0): e = p0 - t(r0)
        {
            float ex[5], ey[5];
            #pragma unroll
            for (int j = 0; j < 5; j++) {
                ex[j] = p0x[j] - t00[j];
                ey[j] = p0y[j] - t10[j];
            }
            bone_sum += bone_reduce(ex, ey, lane);
        }

        if (v_b1) {
            // pose(s0): |p0 - t(r1)|   (invalid lanes hold zeros -> contribute 0)
            #pragma unroll
            for (int j = 0; j < 5; j++) {
                pose_sum += fabsf(p0x[j] - t01[j]) + fabsf(p0y[j] - t11[j]);
            }
            // bone(s1): e = p1 - t(r1)
            float ex[5], ey[5];
            #pragma unroll
            for (int j = 0; j < 5; j++) {
                ex[j] = p1x[j] - t01[j];
                ey[j] = p1y[j] - t11[j];
            }
            bone_sum += bone_reduce(ex, ey, lane);
        }

        if (v_p1) {
            // pose(s1): |p1 - t(r2)|
            #pragma unroll
            for (int j = 0; j < 5; j++) {
                pose_sum += fabsf(p1x[j] - t02[j]) + fabsf(p1y[j] - t12[j]);
            }
        }
    }

    // Warp reduce
    #pragma unroll
    for (int o = 16; o > 0; o >>= 1) {
        pose_sum += __shfl_xor_sync(FULL_MASK, pose_sum, o);
        bone_sum += __shfl_xor_sync(FULL_MASK, bone_sum, o);
    }
    if (lane == 0) {
        s_pose[warp] = pose_sum;
        s_bone[warp] = bone_sum;
    }
    __syncthreads();

    // Block partial + completion ticket
    if (threadIdx.x == 0) {
        float ps = 0.0f, bs = 0.0f;
        #pragma unroll
        for (int w = 0; w < WARPS_PER_BLOCK; w++) {
            ps += s_pose[w];
            bs += s_bone[w];
        }
        g_partials[blockIdx.x] = make_float2(ps, bs);
        __threadfence();
        unsigned old = atomicAdd(&g_counter, 1u);
        s_is_last = (old == (unsigned)(gridDim.x - 1));
    }
    __syncthreads();

    if (!s_is_last) return;

    // ---- Last block: grid-wide final reduction + loss math ----
    __threadfence();

    double dp = 0.0, db = 0.0;
    for (int i = threadIdx.x; i < N_BLOCKS; i += THREADS) {
        float2 v = g_partials[i];
        dp += (double)v.x;
        db += (double)v.y;
    }
    #pragma unroll
    for (int o = 16; o > 0; o >>= 1) {
        dp += __shfl_xor_sync(FULL_MASK, dp, o);
        db += __shfl_xor_sync(FULL_MASK, db, o);
    }
    __shared__ double r_p[WARPS_PER_BLOCK];
    __shared__ double r_b[WARPS_PER_BLOCK];
    __shared__ int    s_len[WARPS_PER_BLOCK];
    if (lane == 0) {
        r_p[warp] = dp;
        r_b[warp] = db;
    }
    {
        int lsum = 0;
        int idx = warp * 16 + lane;
        if (lane < 16) lsum = __ldg(&tlen[idx]);
        #pragma unroll
        for (int o = 16; o > 0; o >>= 1)
            lsum += __shfl_xor_sync(FULL_MASK, lsum, o);
        if (lane == 0) s_len[warp] = lsum;
    }
    __syncthreads();

    if (threadIdx.x == 0) {
        double pose_acc = 0.0, bone_acc = 0.0;
        int len_total = 0;
        #pragma unroll
        for (int w = 0; w < WARPS_PER_BLOCK; w++) {
            pose_acc  += r_p[w];
            bone_acc  += r_b[w];
            len_total += s_len[w];
        }
        double mask_sum = (double)len_total;            // sum(L)
        double pose_den = (double)(len_total - B_DIM);  // sum(L-1)

        double pose_loss = pose_acc / (double)D_DIM / pose_den;
        double bone_loss = bone_acc * 0.5 / ((double)NCONN + 1e-8) / mask_sum;
        double total     = pose_loss + 0.1 * bone_loss;

        out[0] = (float)total;
        out[1] = (float)pose_loss;
        out[2] = (float)bone_loss;

        g_counter = 0;  // reset for next graph replay
    }
}

extern "C" void kernel_launch(void* const* d_in, const int* in_sizes, int n_in,
                              void* d_out, int out_size) {
    const float* pred = (const float*)d_in[0];   // [128, 512, 274] f32
    const float* tgt  = (const float*)d_in[1];   // [128, 2, 512, 137] f32
    const int*   tlen = (const int*)d_in[2];     // [128] i32
    float* out = (float*)d_out;                  // [3] f32: total, pose, bone

    t2p_fused_kernel<<<N_BLOCKS, THREADS>>>(pred, tgt, tlen, out);
}

// round 4
// speedup vs baseline: 1.2981x; 1.2981x over previous
#include <cuda_runtime.h>
#include <cuda_bf16.h>
#include <math.h>

// Problem constants (fixed by the reference)
#define B_DIM 128
#define S_DIM 512
#define K_DIM 137
#define D_DIM (2 * K_DIM)      // 274
#define NCONN (K_DIM - 1)      // 136
#define WARPS_PER_BLOCK 16
#define THREADS (WARPS_PER_BLOCK * 32)       // 512
#define N_ITEMS (B_DIM * S_DIM)              // 65536
#define N_BLOCKS (N_ITEMS / WARPS_PER_BLOCK) // 4096

#define FULL_MASK 0xffffffffu

// Allocation-free scratch. Written unconditionally by every block each run
// (no init kernel needed). Finalize kernel (next graph node) reads it —
// kernel ordering on the stream provides visibility, no fences/atomics.
__device__ float2 g_partials[N_BLOCKS];

// One warp handles one (b, s) item. Bone diffs via register shuffles.
__global__ __launch_bounds__(THREADS) void t2p_main_kernel(
    const float* __restrict__ pred,   // [128, 512, 274]
    const float* __restrict__ tgt,    // [128, 2, 512, 137]
    const int*   __restrict__ tlen)   // [128]
{
    __shared__ float s_pose[WARPS_PER_BLOCK];
    __shared__ float s_bone[WARPS_PER_BLOCK];

    const int warp = threadIdx.x >> 5;
    const int lane = threadIdx.x & 31;
    const int item = blockIdx.x * WARPS_PER_BLOCK + warp;
    const int b = item >> 9;   // item / 512
    const int s = item & 511;  // item % 512

    float pose_sum = 0.0f;
    float bone_sum = 0.0f;

    const int L = __ldg(&tlen[b]);
    const bool bone_valid = (s < L);       // warp-uniform
    const bool pose_valid = (s < L - 1);   // implies s+1 <= S-1 (L <= S)

    if (bone_valid) {
        const float2* __restrict__ p2 = (const float2*)(pred + (size_t)item * D_DIM);
        const float*  __restrict__ t0 = tgt + ((size_t)(2 * b)     * S_DIM + s) * K_DIM;
        const float*  __restrict__ t1 = tgt + ((size_t)(2 * b + 1) * S_DIM + s) * K_DIM;

        // Register-resident errors: lane holds e[k] for k = lane + 32*j.
        float ex[5], ey[5];

        #pragma unroll
        for (int j = 0; j < 4; j++) {
            const int k = lane + 32 * j;
            float2 p  = __ldg(&p2[k]);
            float  a0 = __ldg(&t0[k]);
            float  a1 = __ldg(&t1[k]);
            ex[j] = p.x - a0;
            ey[j] = p.y - a1;
            if (pose_valid) {
                // next timestep rows are contiguous at +K
                pose_sum += fabsf(p.x - __ldg(&t0[k + K_DIM]))
                          + fabsf(p.y - __ldg(&t1[k + K_DIM]));
            }
        }
        // j = 4 partial tail: k = 128 + lane, lanes 0..8 (k <= 136)
        ex[4] = 0.0f; ey[4] = 0.0f;
        if (lane < 9) {
            const int k = 128 + lane;
            float2 p = __ldg(&p2[k]);
            ex[4] = p.x - __ldg(&t0[k]);
            ey[4] = p.y - __ldg(&t1[k]);
            if (pose_valid) {
                pose_sum += fabsf(p.x - __ldg(&t0[k + K_DIM]))
                          + fabsf(p.y - __ldg(&t1[k + K_DIM]));
            }
        }

        // Bone: d[k] = e[k+1] - e[k] via shuffles.
        // e[k+1]: lane<31 -> lane+1 same j; lane==31 -> lane 0 of j+1.
        #pragma unroll
        for (int j = 0; j < 4; j++) {
            float nx_dn = __shfl_down_sync(FULL_MASK, ex[j], 1);
            float ny_dn = __shfl_down_sync(FULL_MASK, ey[j], 1);
            float nx_w0 = __shfl_sync(FULL_MASK, ex[j + 1], 0);
            float ny_w0 = __shfl_sync(FULL_MASK, ey[j + 1], 0);
            float nx = (lane == 31) ? nx_w0 : nx_dn;
            float ny = (lane == 31) ? ny_w0 : ny_dn;
            float dx = nx - ex[j];
            float dy = ny - ey[j];
            bone_sum = fmaf(dx, dx, bone_sum);
            bone_sum = fmaf(dy, dy, bone_sum);
        }
        {   // j = 4: diffs for k = 128..135 -> lanes 0..7
            float nx_dn = __shfl_down_sync(FULL_MASK, ex[4], 1);
            float ny_dn = __shfl_down_sync(FULL_MASK, ey[4], 1);
            if (lane < 8) {
                float dx = nx_dn - ex[4];
                float dy = ny_dn - ey[4];
                bone_sum = fmaf(dx, dx, bone_sum);
                bone_sum = fmaf(dy, dy, bone_sum);
            }
        }
    }

    // Warp reduce
    #pragma unroll
    for (int o = 16; o > 0; o >>= 1) {
        pose_sum += __shfl_xor_sync(FULL_MASK, pose_sum, o);
        bone_sum += __shfl_xor_sync(FULL_MASK, bone_sum, o);
    }
    if (lane == 0) {
        s_pose[warp] = pose_sum;
        s_bone[warp] = bone_sum;
    }
    __syncthreads();

    // Plain per-block partial store — no fence, no atomic, no ticket.
    if (threadIdx.x == 0) {
        float ps = 0.0f, bs = 0.0f;
        #pragma unroll
        for (int w = 0; w < WARPS_PER_BLOCK; w++) {
            ps += s_pose[w];
            bs += s_bone[w];
        }
        g_partials[blockIdx.x] = make_float2(ps, bs);
    }
}

// Single block: reduce 4096 partials (L2-hot) + loss math.
__global__ __launch_bounds__(THREADS) void t2p_finalize_kernel(
    const int* __restrict__ tlen,
    float*     __restrict__ out)
{
    __shared__ double r_p[WARPS_PER_BLOCK];
    __shared__ double r_b[WARPS_PER_BLOCK];
    __shared__ int    s_len;

    const int warp = threadIdx.x >> 5;
    const int lane = threadIdx.x & 31;

    double dp = 0.0, db = 0.0;
    #pragma unroll
    for (int i = threadIdx.x; i < N_BLOCKS; i += THREADS) {
        float2 v = g_partials[i];
        dp += (double)v.x;
        db += (double)v.y;
    }
    #pragma unroll
    for (int o = 16; o > 0; o >>= 1) {
        dp += __shfl_xor_sync(FULL_MASK, dp, o);
        db += __shfl_xor_sync(FULL_MASK, db, o);
    }
    if (lane == 0) {
        r_p[warp] = dp;
        r_b[warp] = db;
    }
    // warp 0 sums target_length (128 ints, 4 per lane)
    if (warp == 0) {
        int lsum = 0;
        #pragma unroll
        for (int i = 0; i < 4; i++) lsum += __ldg(&tlen[lane + 32 * i]);
        #pragma unroll
        for (int o = 16; o > 0; o >>= 1)
            lsum += __shfl_xor_sync(FULL_MASK, lsum, o);
        if (lane == 0) s_len = lsum;
    }
    __syncthreads();

    if (threadIdx.x == 0) {
        double pose_acc = 0.0, bone_acc = 0.0;
        #pragma unroll
        for (int w = 0; w < WARPS_PER_BLOCK; w++) {
            pose_acc += r_p[w];
            bone_acc += r_b[w];
        }
        int len_total = s_len;
        double mask_sum = (double)len_total;            // sum(L)
        double pose_den = (double)(len_total - B_DIM);  // sum(L-1)

        double pose_loss = pose_acc / (double)D_DIM / pose_den;
        double bone_loss = bone_acc * 0.5 / ((double)NCONN + 1e-8) / mask_sum;
        double total     = pose_loss + 0.1 * bone_loss;

        out[0] = (float)total;
        out[1] = (float)pose_loss;
        out[2] = (float)bone_loss;
    }
}

extern "C" void kernel_launch(void* const* d_in, const int* in_sizes, int n_in,
                              void* d_out, int out_size) {
    const float* pred = (const float*)d_in[0];   // [128, 512, 274] f32
    const float* tgt  = (const float*)d_in[1];   // [128, 2, 512, 137] f32
    const int*   tlen = (const int*)d_in[2];     // [128] i32
    float* out = (float*)d_out;                  // [3] f32: total, pose, bone

    t2p_main_kernel<<<N_BLOCKS, THREADS>>>(pred, tgt, tlen);
    t2p_finalize_kernel<<<1, THREADS>>>(tlen, out);
}